// round 2
// baseline (speedup 1.0000x reference)
#include <cuda_runtime.h>

// Inverse 2x2 Haar wavelet transform — R2: streaming cache hints + 2x per-thread work.
// Input  x: [4B, C, H, W] fp32, quadrants k=0..3 at offset k*B*C*H*W
// Output  : [B, C, 2H, 2W] fp32
//
// Each thread: 8 consecutive j of one (b,c,i) row.
//   loads : 8 x LDG.128 (.cs)  (2 per quadrant)
//   stores: 8 x STG.128 (.cs)  (4 per output row, rows 2i and 2i+1)

static constexpr int H = 128;
static constexpr int W = 128;
static constexpr int W8 = W / 8;              // 16 groups of 8 floats per input row
static constexpr long long PLANE_IN  = (long long)H * W;         // 16384
static constexpr long long PLANE_OUT = (long long)(2*H) * (2*W); // 65536

__device__ __forceinline__ float4 ldcs4(const float* p) {
    return __ldcs((const float4*)p);
}
__device__ __forceinline__ void stcs4(float* p, float4 v) {
    __stcs((float4*)p, v);
}

__global__ __launch_bounds__(256)
void iwt_kernel(const float* __restrict__ x, float* __restrict__ out,
                long long quad_stride,   // B*C*H*W elements between quadrants
                int n_threads)           // planes * H * W8
{
    int tid = blockIdx.x * blockDim.x + threadIdx.x;
    if (tid >= n_threads) return;

    // tid -> (plane, i, j8)
    int j8    = tid & (W8 - 1);          // W8 = 16
    int rest  = tid >> 4;
    int i     = rest & (H - 1);          // H = 128
    int plane = rest >> 7;

    long long in_off = (long long)plane * PLANE_IN + (long long)i * W + (long long)j8 * 8;

    const float* p1 = x + in_off;
    const float* p2 = p1 + quad_stride;
    const float* p3 = p2 + quad_stride;
    const float* p4 = p3 + quad_stride;

    // 8 independent 128-bit loads, batched up front for MLP
    float4 a0 = ldcs4(p1);     float4 a1 = ldcs4(p1 + 4);
    float4 b0 = ldcs4(p2);     float4 b1 = ldcs4(p2 + 4);
    float4 c0 = ldcs4(p3);     float4 c1 = ldcs4(p3 + 4);
    float4 d0 = ldcs4(p4);     float4 d1 = ldcs4(p4 + 4);

    float ax[8] = {a0.x,a0.y,a0.z,a0.w, a1.x,a1.y,a1.z,a1.w};
    float bx[8] = {b0.x,b0.y,b0.z,b0.w, b1.x,b1.y,b1.z,b1.w};
    float cx[8] = {c0.x,c0.y,c0.z,c0.w, c1.x,c1.y,c1.z,c1.w};
    float dx[8] = {d0.x,d0.y,d0.z,d0.w, d1.x,d1.y,d1.z,d1.w};

    float e00[8], e01[8], e10[8], e11[8];
    #pragma unroll
    for (int l = 0; l < 8; l++) {
        float s_ad = ax[l] + dx[l];   // x1 + x4
        float d_ad = ax[l] - dx[l];   // x1 - x4
        float s_bc = bx[l] + cx[l];   // x2 + x3
        float d_bc = bx[l] - cx[l];   // x2 - x3
        e00[l] = 0.5f * (s_ad - s_bc);   // x1 - x2 - x3 + x4
        e01[l] = 0.5f * (d_ad + d_bc);   // x1 + x2 - x3 - x4
        e10[l] = 0.5f * (d_ad - d_bc);   // x1 - x2 + x3 - x4
        e11[l] = 0.5f * (s_ad + s_bc);   // x1 + x2 + x3 + x4
    }

    // output: rows 2i and 2i+1, cols 16*j8 .. 16*j8+15 (16 floats per row = 4 float4)
    long long out_base = (long long)plane * PLANE_OUT
                       + (long long)(2 * i) * (2 * W)
                       + (long long)j8 * 16;
    float* o0 = out + out_base;           // row 2i
    float* o1 = o0 + 2 * W;               // row 2i+1

    #pragma unroll
    for (int g = 0; g < 4; g++) {
        // group g covers input lanes 2g, 2g+1 -> output cols 4g..4g+3
        stcs4(o0 + 4*g, make_float4(e00[2*g], e01[2*g], e00[2*g+1], e01[2*g+1]));
        stcs4(o1 + 4*g, make_float4(e10[2*g], e11[2*g], e10[2*g+1], e11[2*g+1]));
    }
}

extern "C" void kernel_launch(void* const* d_in, const int* in_sizes, int n_in,
                              void* d_out, int out_size) {
    const float* x = (const float*)d_in[0];
    float* out = (float*)d_out;

    long long total = (long long)in_sizes[0];
    long long quad_stride = total / 4;          // B*C*H*W
    long long planes = quad_stride / PLANE_IN;  // B*C
    int n_threads = (int)(planes * H * W8);

    int block = 256;
    int grid = (n_threads + block - 1) / block;
    iwt_kernel<<<grid, block>>>(x, out, quad_stride, n_threads);
}

// round 3
// speedup vs baseline: 1.1130x; 1.1130x over previous
#include <cuda_runtime.h>

// Inverse 2x2 Haar wavelet transform — R3: R1 shape (4 floats/thread, occ-friendly)
// + streaming cache hints (.cs) as the single changed variable vs R1.
//
// Input  x: [4B, C, H, W] fp32, quadrants k=0..3 at offset k*B*C*H*W
// Output  : [B, C, 2H, 2W] fp32

static constexpr int H = 128;
static constexpr int W = 128;
static constexpr int W4 = W / 4;              // float4 groups per input row
static constexpr long long PLANE_IN  = (long long)H * W;         // 16384
static constexpr long long PLANE_OUT = (long long)(2*H) * (2*W); // 65536

__global__ __launch_bounds__(256)
void iwt_kernel(const float* __restrict__ x, float* __restrict__ out,
                long long quad_stride,   // B*C*H*W elements between quadrants
                int n_threads)           // planes * H * W4
{
    int tid = blockIdx.x * blockDim.x + threadIdx.x;
    if (tid >= n_threads) return;

    // tid -> (plane, i, j4)
    int j4    = tid & (W4 - 1);          // W4 = 32
    int rest  = tid >> 5;
    int i     = rest & (H - 1);          // H = 128
    int plane = rest >> 7;

    long long in_off = (long long)plane * PLANE_IN + (long long)i * W + (long long)j4 * 4;

    const float4 a = __ldcs((const float4*)(x + in_off));                    // x1
    const float4 b = __ldcs((const float4*)(x + in_off + quad_stride));      // x2
    const float4 c = __ldcs((const float4*)(x + in_off + 2 * quad_stride));  // x3
    const float4 d = __ldcs((const float4*)(x + in_off + 3 * quad_stride));  // x4

    float e00[4], e01[4], e10[4], e11[4];
    {
        const float ax[4] = {a.x, a.y, a.z, a.w};
        const float bx[4] = {b.x, b.y, b.z, b.w};
        const float cx[4] = {c.x, c.y, c.z, c.w};
        const float dx[4] = {d.x, d.y, d.z, d.w};
        #pragma unroll
        for (int l = 0; l < 4; l++) {
            float s_ad = ax[l] + dx[l];   // x1 + x4
            float d_ad = ax[l] - dx[l];   // x1 - x4
            float s_bc = bx[l] + cx[l];   // x2 + x3
            float d_bc = bx[l] - cx[l];   // x2 - x3
            e00[l] = 0.5f * (s_ad - s_bc);   // x1 - x2 - x3 + x4
            e01[l] = 0.5f * (d_ad + d_bc);   // x1 + x2 - x3 - x4
            e10[l] = 0.5f * (d_ad - d_bc);   // x1 - x2 + x3 - x4
            e11[l] = 0.5f * (s_ad + s_bc);   // x1 + x2 + x3 + x4
        }
    }

    // output: rows 2i and 2i+1, cols 8*j4 .. 8*j4+7
    long long out_base = (long long)plane * PLANE_OUT
                       + (long long)(2 * i) * (2 * W)
                       + (long long)j4 * 8;

    __stcs((float4*)(out + out_base),             make_float4(e00[0], e01[0], e00[1], e01[1]));
    __stcs((float4*)(out + out_base + 4),         make_float4(e00[2], e01[2], e00[3], e01[3]));
    __stcs((float4*)(out + out_base + 2*W),       make_float4(e10[0], e11[0], e10[1], e11[1]));
    __stcs((float4*)(out + out_base + 2*W + 4),   make_float4(e10[2], e11[2], e10[3], e11[3]));
}

extern "C" void kernel_launch(void* const* d_in, const int* in_sizes, int n_in,
                              void* d_out, int out_size) {
    const float* x = (const float*)d_in[0];
    float* out = (float*)d_out;

    long long total = (long long)in_sizes[0];
    long long quad_stride = total / 4;          // B*C*H*W
    long long planes = quad_stride / PLANE_IN;  // B*C
    int n_threads = (int)(planes * H * W4);

    int block = 256;
    int grid = (n_threads + block - 1) / block;
    iwt_kernel<<<grid, block>>>(x, out, quad_stride, n_threads);
}

// round 4
// speedup vs baseline: 1.2180x; 1.0944x over previous
#include <cuda_runtime.h>

// Inverse 2x2 Haar wavelet transform — R4: lane-contiguous stores.
// Input  x: [4B, C, H, W] fp32, quadrants k=0..3 at offset k*B*C*H*W
// Output  : [B, C, 2H, 2W] fp32
//
// Each thread handles 2 consecutive input j (j = 2t, 2t+1) of one (plane, i) row:
//   loads : 4 x LDG.64  (float2 per quadrant; 8B lane stride -> fully coalesced)
//   stores: 2 x STG.128 (one float4 per output row; 16B lane stride -> fully
//           contiguous 512B per warp per store, fixing R1's half-width stores)

static constexpr int H = 128;
static constexpr int W = 128;
static constexpr int W2 = W / 2;              // 64 j-pairs per input row
static constexpr long long PLANE_IN  = (long long)H * W;         // 16384
static constexpr long long PLANE_OUT = (long long)(2*H) * (2*W); // 65536

__global__ __launch_bounds__(256)
void iwt_kernel(const float* __restrict__ x, float* __restrict__ out,
                long long quad_stride,   // B*C*H*W elements between quadrants
                int n_threads)           // planes * H * W2
{
    int tid = blockIdx.x * blockDim.x + threadIdx.x;
    if (tid >= n_threads) return;

    // tid -> (plane, i, j2)
    int j2    = tid & (W2 - 1);          // 0..63
    int rest  = tid >> 6;
    int i     = rest & (H - 1);          // 0..127
    int plane = rest >> 7;

    long long in_off = (long long)plane * PLANE_IN + (long long)i * W + (long long)j2 * 2;

    const float2 a = __ldg((const float2*)(x + in_off));                    // x1
    const float2 b = __ldg((const float2*)(x + in_off + quad_stride));      // x2
    const float2 c = __ldg((const float2*)(x + in_off + 2 * quad_stride));  // x3
    const float2 d = __ldg((const float2*)(x + in_off + 3 * quad_stride));  // x4

    const float ax[2] = {a.x, a.y};
    const float bx[2] = {b.x, b.y};
    const float cx[2] = {c.x, c.y};
    const float dx[2] = {d.x, d.y};

    float e00[2], e01[2], e10[2], e11[2];
    #pragma unroll
    for (int l = 0; l < 2; l++) {
        float s_ad = ax[l] + dx[l];   // x1 + x4
        float d_ad = ax[l] - dx[l];   // x1 - x4
        float s_bc = bx[l] + cx[l];   // x2 + x3
        float d_bc = bx[l] - cx[l];   // x2 - x3
        e00[l] = 0.5f * (s_ad - s_bc);   // x1 - x2 - x3 + x4
        e01[l] = 0.5f * (d_ad + d_bc);   // x1 + x2 - x3 - x4
        e10[l] = 0.5f * (d_ad - d_bc);   // x1 - x2 + x3 - x4
        e11[l] = 0.5f * (s_ad + s_bc);   // x1 + x2 + x3 + x4
    }

    // output rows 2i and 2i+1, cols 4*j2 .. 4*j2+3 (one float4 each)
    long long out_base = (long long)plane * PLANE_OUT
                       + (long long)(2 * i) * (2 * W)
                       + (long long)j2 * 4;

    *(float4*)(out + out_base)         = make_float4(e00[0], e01[0], e00[1], e01[1]);
    *(float4*)(out + out_base + 2*W)   = make_float4(e10[0], e11[0], e10[1], e11[1]);
}

extern "C" void kernel_launch(void* const* d_in, const int* in_sizes, int n_in,
                              void* d_out, int out_size) {
    const float* x = (const float*)d_in[0];
    float* out = (float*)d_out;

    long long total = (long long)in_sizes[0];
    long long quad_stride = total / 4;          // B*C*H*W
    long long planes = quad_stride / PLANE_IN;  // B*C
    int n_threads = (int)(planes * H * W2);

    int block = 256;
    int grid = (n_threads + block - 1) / block;
    iwt_kernel<<<grid, block>>>(x, out, quad_stride, n_threads);
}